// round 17
// baseline (speedup 1.0000x reference)
#include <cuda_runtime.h>

// DropBlock, balanced one-wave persistent kernel:
//   GRID=784 CTAs x 8 tiles x (256 thr x V4=4) = 6,422,528 float4 EXACTLY
//   -> zero remainder, zero tail. 784 CTAs co-resident in ONE wave at
//   6 CTAs/SM, enforced by __launch_bounds__(256, 6) (regs <= 42; any
//   spill lands in the once-per-CTA prologue, not the stream loop).
//   Steady state = the best-measured apply shape: 4 front-batched __ldcs
//   loads -> 4 mul + __stcs stores, mask via conflict-free LDS.
// GAMMA = 0.1/49 * (56^2/50^2) = 0.00256 exactly.

#define H 56
#define W 56
#define HW 3136          // 56*56
#define HW4 784          // HW/4
#define GAMMA 0.00256f
#define THREADS 256
#define V4 4
#define V4_PER_TILE (THREADS * V4)   // 1024
#define TILES_PER_CTA 8
#define GRID 784

__global__ void __launch_bounds__(THREADS, 6) dropblock_persist(
    const float4* __restrict__ x, const float4* __restrict__ u4,
    float4* __restrict__ out) {
    // 12.5KB buffer reused: u floats (prologue) then mask float4s (loop)
    __shared__ __align__(16) float s_buf[HW];
    __shared__ unsigned long long rowd[H];
    __shared__ unsigned long long dil[H];
    __shared__ int partial[2];

    const int tid = threadIdx.x;

    // ── 1. front-batch FIRST tile's 4 loads (before any barrier) ──
    int base = blockIdx.x * (TILES_PER_CTA * V4_PER_TILE) + tid;
    float4 v[V4];
    #pragma unroll
    for (int k = 0; k < V4; ++k)
        v[k] = __ldcs(&x[base + k * THREADS]);

    // ── 2. stage u into shared (784 float4, coalesced) ──
    float4* s_buf4 = reinterpret_cast<float4*>(s_buf);
    #pragma unroll
    for (int j = 0; j < 4; ++j) {
        const int i = tid + j * THREADS;
        if (i < HW4) s_buf4[i] = __ldg(&u4[i]);
    }
    __syncthreads();

    // ── 3. row-wise backward dilation (width 7) as bit ops ──
    if (tid < H) {
        unsigned long long s = 0ULL;
        #pragma unroll
        for (int w = 0; w < W; ++w)
            s |= (unsigned long long)(s_buf[tid * W + w] < GAMMA) << w;
        unsigned long long a = s | (s << 1);     // shifts {0,1}
        unsigned long long b = a | (a << 2);     // shifts {0..3}
        unsigned long long c = b | (b << 3);     // shifts {0..6}
        rowd[tid] = c & ((1ULL << W) - 1ULL);
    }
    __syncthreads();

    // ── 4. column phase + shuffle-reduced popcount (two FULL warps) ──
    if (tid < 64) {
        int p = 0;
        if (tid < H) {
            const int h0 = tid - 6 < 0 ? 0 : tid - 6;
            unsigned long long d = 0ULL;
            for (int h = h0; h <= tid; ++h) d |= rowd[h];
            dil[tid] = d;
            p = __popcll(d);
        }
        #pragma unroll
        for (int off = 16; off > 0; off >>= 1)
            p += __shfl_down_sync(0xFFFFFFFFu, p, off);
        if ((tid & 31) == 0) partial[tid >> 5] = p;
    }
    __syncthreads();

    // ── 5. scale + mask float4s over dead u buffer ──
    const float scale = (float)HW / (float)(HW - partial[0] - partial[1]);
    #pragma unroll
    for (int j = 0; j < 4; ++j) {
        const int s4 = tid + j * THREADS;
        if (s4 < HW4) {
            const int h = s4 / 14;               // 14 float4 per row
            const int w0 = (s4 % 14) * 4;
            const unsigned long long bits = dil[h] >> w0;
            float4 mk;
            mk.x = (bits & 1ULL) ? 0.0f : scale;
            mk.y = (bits & 2ULL) ? 0.0f : scale;
            mk.z = (bits & 4ULL) ? 0.0f : scale;
            mk.w = (bits & 8ULL) ? 0.0f : scale;
            s_buf4[s4] = mk;
        }
    }
    __syncthreads();

    // ── 6. exactly 8 tiles per CTA; consume tile t, then load tile t+1 ──
    int s4 = base % HW4;
    #pragma unroll 1
    for (int t = 0; t < TILES_PER_CTA; ++t) {
        #pragma unroll
        for (int k = 0; k < V4; ++k) {
            const float4 mk = s_buf4[s4];
            v[k].x *= mk.x; v[k].y *= mk.y; v[k].z *= mk.z; v[k].w *= mk.w;
            __stcs(&out[base + k * THREADS], v[k]);
            s4 += THREADS;
            if (s4 >= HW4) s4 -= HW4;
        }
        if (t + 1 < TILES_PER_CTA) {
            base += V4_PER_TILE;
            #pragma unroll
            for (int k = 0; k < V4; ++k)
                v[k] = __ldcs(&x[base + k * THREADS]);
        }
    }
}

extern "C" void kernel_launch(void* const* d_in, const int* in_sizes, int n_in,
                              void* d_out, int out_size) {
    const float* x = (const float*)d_in[0];   // (32,256,56,56) f32
    const float* u = (const float*)d_in[1];   // (56,56) f32

    dropblock_persist<<<GRID, THREADS>>>(
        (const float4*)x, (const float4*)u, (float4*)d_out);
}